// round 5
// baseline (speedup 1.0000x reference)
#include <cuda_runtime.h>
#include <math.h>

// Problem constants
#define BATCH 4
#define SEQ   4096
#define DDIM  256
#define HDIM  1024
#define TAPS  15          // K = 2*W+1, W=7
#define MROWS (BATCH*SEQ) // 16384

// GEMM tile config
#define BM 128
#define BN 128
#define BKK 8

// Scratch (static device globals — no runtime allocation).
// NOTE: these must ONLY be referenced from device code. Passing them as
// kernel args from host code passes the host shadow address, which on
// GB300 (ATS) silently dereferences host memory — the R4 bug.
__device__ float g_U  [MROWS * DDIM];   // x + mix
__device__ float g_Hh [MROWS * DDIM];   // LN1 output
__device__ float g_Act[MROWS * HDIM];   // gelu(h @ W1 + b1)
__device__ float g_V  [MROWS * DDIM];   // h + ff

// ---------------------------------------------------------------------------
// Kernel 1: mix GEMM (causal local conv as im2col GEMM) + residual add
//   U[r, j] = x[r, j] + b_mix[j] + sum_{tap,d} x[b, n+tap-14, d] * w_mix[tap,d,j]
// Grid: (MROWS/BM, DDIM/BN) = (128, 2), 256 threads.
// ---------------------------------------------------------------------------
__global__ void mix_gemm_kernel(const float* __restrict__ x,
                                const float* __restrict__ w_mix,
                                const float* __restrict__ b_mix)
{
    __shared__ float As[BKK][BM];
    __shared__ float Bs[BKK][BN];

    const int tid = threadIdx.x;
    const int bm  = blockIdx.x * BM;          // global row base (0..16383)
    const int bn  = blockIdx.y * BN;          // output col base (0 or 128)

    const int tx = tid & 15;                  // 0..15 (col group)
    const int ty = tid >> 4;                  // 0..15 (row group)

    const int a_row = tid >> 1;               // 0..127
    const int a_col = (tid & 1) * 4;          // 0 or 4
    const int b_row = tid >> 5;               // 0..7
    const int b_col = (tid & 31) * 4;         // 0..124

    // Whole block is within one batch (4096 % 128 == 0)
    const int bidx   = bm / SEQ;
    const int n_base = bm % SEQ;
    const float* xb  = x + (size_t)bidx * SEQ * DDIM;

    float acc[8][8];
#pragma unroll
    for (int i = 0; i < 8; i++)
#pragma unroll
        for (int j = 0; j < 8; j++) acc[i][j] = 0.0f;

    for (int tap = 0; tap < TAPS; tap++) {
        const int src_off = tap - 14;                       // causal offset
        const float* wtap = w_mix + (size_t)tap * DDIM * DDIM;
        for (int d0 = 0; d0 < DDIM; d0 += BKK) {
            // A gather: x[b, n + tap - 14, d0+a_col .. +3] (zero if src < 0)
            {
                const int src = n_base + a_row + src_off;
                float4 av = make_float4(0.f, 0.f, 0.f, 0.f);
                if (src >= 0)
                    av = *(const float4*)&xb[(size_t)src * DDIM + d0 + a_col];
                As[a_col + 0][a_row] = av.x;
                As[a_col + 1][a_row] = av.y;
                As[a_col + 2][a_row] = av.z;
                As[a_col + 3][a_row] = av.w;
            }
            // B load: w_mix[tap, d0+b_row, bn+b_col..+3]
            {
                float4 bv = *(const float4*)&wtap[(size_t)(d0 + b_row) * DDIM + bn + b_col];
                *(float4*)&Bs[b_row][b_col] = bv;
            }
            __syncthreads();
#pragma unroll
            for (int kk = 0; kk < BKK; kk++) {
                float4 a0 = *(const float4*)&As[kk][ty * 8];
                float4 a1 = *(const float4*)&As[kk][ty * 8 + 4];
                float4 b0 = *(const float4*)&Bs[kk][tx * 8];
                float4 b1 = *(const float4*)&Bs[kk][tx * 8 + 4];
                float ar[8] = {a0.x, a0.y, a0.z, a0.w, a1.x, a1.y, a1.z, a1.w};
                float br[8] = {b0.x, b0.y, b0.z, b0.w, b1.x, b1.y, b1.z, b1.w};
#pragma unroll
                for (int i = 0; i < 8; i++)
#pragma unroll
                    for (int j = 0; j < 8; j++)
                        acc[i][j] = fmaf(ar[i], br[j], acc[i][j]);
            }
            __syncthreads();
        }
    }

    // Epilogue: + b_mix + x residual -> g_U
#pragma unroll
    for (int i = 0; i < 8; i++) {
        const int row = bm + ty * 8 + i;
#pragma unroll
        for (int j4 = 0; j4 < 8; j4 += 4) {
            const int col = bn + tx * 8 + j4;
            float4 xr = *(const float4*)&x[(size_t)row * DDIM + col];
            float4 bb = *(const float4*)&b_mix[col];
            float4 o;
            o.x = acc[i][j4 + 0] + bb.x + xr.x;
            o.y = acc[i][j4 + 1] + bb.y + xr.y;
            o.z = acc[i][j4 + 2] + bb.z + xr.z;
            o.w = acc[i][j4 + 3] + bb.w + xr.w;
            *(float4*)&g_U[(size_t)row * DDIM + col] = o;
        }
    }
}

// ---------------------------------------------------------------------------
// LayerNorm over last dim (256). One 256-thread block per row.
// Device helper; in/out bound to __device__ globals inside device code.
// ---------------------------------------------------------------------------
__device__ __forceinline__ void ln_row(const float* __restrict__ in,
                                       const float* __restrict__ g,
                                       const float* __restrict__ b,
                                       float* __restrict__ out)
{
    const int row = blockIdx.x;
    const int t   = threadIdx.x;
    float v = in[(size_t)row * DDIM + t];

    float s = v;
#pragma unroll
    for (int o = 16; o > 0; o >>= 1) s += __shfl_xor_sync(0xffffffffu, s, o);
    __shared__ float r1[8], r2[8];
    if ((t & 31) == 0) r1[t >> 5] = s;
    __syncthreads();
    float tot = 0.0f;
#pragma unroll
    for (int i = 0; i < 8; i++) tot += r1[i];
    const float mu = tot * (1.0f / 256.0f);

    const float d = v - mu;
    float s2 = d * d;
#pragma unroll
    for (int o = 16; o > 0; o >>= 1) s2 += __shfl_xor_sync(0xffffffffu, s2, o);
    if ((t & 31) == 0) r2[t >> 5] = s2;
    __syncthreads();
    float tv = 0.0f;
#pragma unroll
    for (int i = 0; i < 8; i++) tv += r2[i];
    const float var = tv * (1.0f / 256.0f);

    out[(size_t)row * DDIM + t] = d * rsqrtf(var + 1e-5f) * g[t] + b[t];
}

// LN1: g_U -> g_Hh (globals referenced in device code — valid device addresses)
__global__ void ln1_kernel(const float* __restrict__ g,
                           const float* __restrict__ b)
{
    ln_row(g_U, g, b, g_Hh);
}

// LN2: g_V -> out (out is the harness's d_out, a real device pointer)
__global__ void ln2_kernel(const float* __restrict__ g,
                           const float* __restrict__ b,
                           float* __restrict__ out)
{
    ln_row(g_V, g, b, out);
}

// ---------------------------------------------------------------------------
// Kernel 3: FFN1 = gelu(h @ W1 + b_ff1)   [16384 x 256] @ [256 x 1024]
// Grid: (128, 8), 256 threads.
// ---------------------------------------------------------------------------
__global__ void ffn1_kernel(const float* __restrict__ W1,
                            const float* __restrict__ bff1)
{
    __shared__ float As[BKK][BM];
    __shared__ float Bs[BKK][BN];

    const int tid = threadIdx.x;
    const int bm  = blockIdx.x * BM;
    const int bn  = blockIdx.y * BN;
    const int tx  = tid & 15;
    const int ty  = tid >> 4;
    const int a_row = tid >> 1;
    const int a_col = (tid & 1) * 4;
    const int b_row = tid >> 5;
    const int b_col = (tid & 31) * 4;

    float acc[8][8];
#pragma unroll
    for (int i = 0; i < 8; i++)
#pragma unroll
        for (int j = 0; j < 8; j++) acc[i][j] = 0.0f;

    for (int k0 = 0; k0 < DDIM; k0 += BKK) {
        float4 av = *(const float4*)&g_Hh[(size_t)(bm + a_row) * DDIM + k0 + a_col];
        As[a_col + 0][a_row] = av.x;
        As[a_col + 1][a_row] = av.y;
        As[a_col + 2][a_row] = av.z;
        As[a_col + 3][a_row] = av.w;
        float4 bv = *(const float4*)&W1[(size_t)(k0 + b_row) * HDIM + bn + b_col];
        *(float4*)&Bs[b_row][b_col] = bv;
        __syncthreads();
#pragma unroll
        for (int kk = 0; kk < BKK; kk++) {
            float4 a0 = *(const float4*)&As[kk][ty * 8];
            float4 a1 = *(const float4*)&As[kk][ty * 8 + 4];
            float4 b0 = *(const float4*)&Bs[kk][tx * 8];
            float4 b1 = *(const float4*)&Bs[kk][tx * 8 + 4];
            float ar[8] = {a0.x, a0.y, a0.z, a0.w, a1.x, a1.y, a1.z, a1.w};
            float br[8] = {b0.x, b0.y, b0.z, b0.w, b1.x, b1.y, b1.z, b1.w};
#pragma unroll
            for (int i = 0; i < 8; i++)
#pragma unroll
                for (int j = 0; j < 8; j++)
                    acc[i][j] = fmaf(ar[i], br[j], acc[i][j]);
        }
        __syncthreads();
    }

#pragma unroll
    for (int i = 0; i < 8; i++) {
        const int row = bm + ty * 8 + i;
#pragma unroll
        for (int j4 = 0; j4 < 8; j4 += 4) {
            const int col = bn + tx * 8 + j4;
            float4 bb = *(const float4*)&bff1[col];
            float4 o;
            float vx = acc[i][j4 + 0] + bb.x;
            float vy = acc[i][j4 + 1] + bb.y;
            float vz = acc[i][j4 + 2] + bb.z;
            float vw = acc[i][j4 + 3] + bb.w;
            // exact GELU: 0.5*x*(1+erf(x/sqrt(2)))
            o.x = 0.5f * vx * (1.0f + erff(vx * 0.70710678118654752f));
            o.y = 0.5f * vy * (1.0f + erff(vy * 0.70710678118654752f));
            o.z = 0.5f * vz * (1.0f + erff(vz * 0.70710678118654752f));
            o.w = 0.5f * vw * (1.0f + erff(vw * 0.70710678118654752f));
            *(float4*)&g_Act[(size_t)row * HDIM + col] = o;
        }
    }
}

// ---------------------------------------------------------------------------
// Kernel 4: FFN2 = Act @ W2 + b_ff2 + h   [16384 x 1024] @ [1024 x 256]
// Grid: (128, 2), 256 threads.
// ---------------------------------------------------------------------------
__global__ void ffn2_kernel(const float* __restrict__ W2,
                            const float* __restrict__ bff2)
{
    __shared__ float As[BKK][BM];
    __shared__ float Bs[BKK][BN];

    const int tid = threadIdx.x;
    const int bm  = blockIdx.x * BM;
    const int bn  = blockIdx.y * BN;
    const int tx  = tid & 15;
    const int ty  = tid >> 4;
    const int a_row = tid >> 1;
    const int a_col = (tid & 1) * 4;
    const int b_row = tid >> 5;
    const int b_col = (tid & 31) * 4;

    float acc[8][8];
#pragma unroll
    for (int i = 0; i < 8; i++)
#pragma unroll
        for (int j = 0; j < 8; j++) acc[i][j] = 0.0f;

    for (int k0 = 0; k0 < HDIM; k0 += BKK) {
        float4 av = *(const float4*)&g_Act[(size_t)(bm + a_row) * HDIM + k0 + a_col];
        As[a_col + 0][a_row] = av.x;
        As[a_col + 1][a_row] = av.y;
        As[a_col + 2][a_row] = av.z;
        As[a_col + 3][a_row] = av.w;
        float4 bv = *(const float4*)&W2[(size_t)(k0 + b_row) * DDIM + bn + b_col];
        *(float4*)&Bs[b_row][b_col] = bv;
        __syncthreads();
#pragma unroll
        for (int kk = 0; kk < BKK; kk++) {
            float4 a0 = *(const float4*)&As[kk][ty * 8];
            float4 a1 = *(const float4*)&As[kk][ty * 8 + 4];
            float4 b0 = *(const float4*)&Bs[kk][tx * 8];
            float4 b1 = *(const float4*)&Bs[kk][tx * 8 + 4];
            float ar[8] = {a0.x, a0.y, a0.z, a0.w, a1.x, a1.y, a1.z, a1.w};
            float br[8] = {b0.x, b0.y, b0.z, b0.w, b1.x, b1.y, b1.z, b1.w};
#pragma unroll
            for (int i = 0; i < 8; i++)
#pragma unroll
                for (int j = 0; j < 8; j++)
                    acc[i][j] = fmaf(ar[i], br[j], acc[i][j]);
        }
        __syncthreads();
    }

    // Epilogue: + b_ff2 + h residual -> g_V
#pragma unroll
    for (int i = 0; i < 8; i++) {
        const int row = bm + ty * 8 + i;
#pragma unroll
        for (int j4 = 0; j4 < 8; j4 += 4) {
            const int col = bn + tx * 8 + j4;
            float4 hr = *(const float4*)&g_Hh[(size_t)row * DDIM + col];
            float4 bb = *(const float4*)&bff2[col];
            float4 o;
            o.x = acc[i][j4 + 0] + bb.x + hr.x;
            o.y = acc[i][j4 + 1] + bb.y + hr.y;
            o.z = acc[i][j4 + 2] + bb.z + hr.z;
            o.w = acc[i][j4 + 3] + bb.w + hr.w;
            *(float4*)&g_V[(size_t)row * DDIM + col] = o;
        }
    }
}

// ---------------------------------------------------------------------------
extern "C" void kernel_launch(void* const* d_in, const int* in_sizes, int n_in,
                              void* d_out, int out_size)
{
    const float* x     = (const float*)d_in[0];
    const float* w_mix = (const float*)d_in[1];
    const float* b_mix = (const float*)d_in[2];
    const float* g1    = (const float*)d_in[3];
    const float* b1    = (const float*)d_in[4];
    const float* w_ff1 = (const float*)d_in[5];
    const float* b_ff1 = (const float*)d_in[6];
    const float* w_ff2 = (const float*)d_in[7];
    const float* b_ff2 = (const float*)d_in[8];
    const float* g2    = (const float*)d_in[9];
    const float* b2    = (const float*)d_in[10];
    float* out = (float*)d_out;

    dim3 block(256);

    // 1) mix conv-GEMM + residual -> g_U
    mix_gemm_kernel<<<dim3(MROWS / BM, DDIM / BN), block>>>(x, w_mix, b_mix);
    // 2) LN1: g_U -> g_Hh
    ln1_kernel<<<MROWS, 256>>>(g1, b1);
    // 3) FFN1 + GELU -> g_Act
    ffn1_kernel<<<dim3(MROWS / BM, HDIM / BN), block>>>(w_ff1, b_ff1);
    // 4) FFN2 + residual -> g_V
    ffn2_kernel<<<dim3(MROWS / BM, DDIM / BN), block>>>(w_ff2, b_ff2);
    // 5) LN2: g_V -> out
    ln2_kernel<<<MROWS, 256>>>(g2, b2, out);
}

// round 6
// speedup vs baseline: 1.0037x; 1.0037x over previous
#include <cuda_runtime.h>
#include <math.h>

// Problem constants
#define BATCH 4
#define SEQ   4096
#define DDIM  256
#define HDIM  1024
#define TAPS  15          // K = 2*W+1, W=7
#define MROWS (BATCH*SEQ) // 16384

// GEMM tile config
#define BM 128
#define BN 128
#define BKK 8

// Scratch (static device globals — no runtime allocation).
// NOTE: these must ONLY be referenced from device code. Passing them as
// kernel args from host code passes the host shadow address, which on
// GB300 (ATS) silently dereferences host memory — the R4 bug.
__device__ float g_U  [MROWS * DDIM];   // x + mix
__device__ float g_Hh [MROWS * DDIM];   // LN1 output
__device__ float g_Act[MROWS * HDIM];   // gelu(h @ W1 + b1)
__device__ float g_V  [MROWS * DDIM];   // h + ff

// ---------------------------------------------------------------------------
// Kernel 1: mix GEMM (causal local conv as im2col GEMM) + residual add
//   U[r, j] = x[r, j] + b_mix[j] + sum_{tap,d} x[b, n+tap-14, d] * w_mix[tap,d,j]
// Grid: (MROWS/BM, DDIM/BN) = (128, 2), 256 threads.
// ---------------------------------------------------------------------------
__global__ void mix_gemm_kernel(const float* __restrict__ x,
                                const float* __restrict__ w_mix,
                                const float* __restrict__ b_mix)
{
    __shared__ float As[BKK][BM];
    __shared__ float Bs[BKK][BN];

    const int tid = threadIdx.x;
    const int bm  = blockIdx.x * BM;          // global row base (0..16383)
    const int bn  = blockIdx.y * BN;          // output col base (0 or 128)

    const int tx = tid & 15;                  // 0..15 (col group)
    const int ty = tid >> 4;                  // 0..15 (row group)

    const int a_row = tid >> 1;               // 0..127
    const int a_col = (tid & 1) * 4;          // 0 or 4
    const int b_row = tid >> 5;               // 0..7
    const int b_col = (tid & 31) * 4;         // 0..124

    // Whole block is within one batch (4096 % 128 == 0)
    const int bidx   = bm / SEQ;
    const int n_base = bm % SEQ;
    const float* xb  = x + (size_t)bidx * SEQ * DDIM;

    float acc[8][8];
#pragma unroll
    for (int i = 0; i < 8; i++)
#pragma unroll
        for (int j = 0; j < 8; j++) acc[i][j] = 0.0f;

    for (int tap = 0; tap < TAPS; tap++) {
        const int src_off = tap - 14;                       // causal offset
        const float* wtap = w_mix + (size_t)tap * DDIM * DDIM;
        for (int d0 = 0; d0 < DDIM; d0 += BKK) {
            // A gather: x[b, n + tap - 14, d0+a_col .. +3] (zero if src < 0)
            {
                const int src = n_base + a_row + src_off;
                float4 av = make_float4(0.f, 0.f, 0.f, 0.f);
                if (src >= 0)
                    av = *(const float4*)&xb[(size_t)src * DDIM + d0 + a_col];
                As[a_col + 0][a_row] = av.x;
                As[a_col + 1][a_row] = av.y;
                As[a_col + 2][a_row] = av.z;
                As[a_col + 3][a_row] = av.w;
            }
            // B load: w_mix[tap, d0+b_row, bn+b_col..+3]
            {
                float4 bv = *(const float4*)&wtap[(size_t)(d0 + b_row) * DDIM + bn + b_col];
                *(float4*)&Bs[b_row][b_col] = bv;
            }
            __syncthreads();
#pragma unroll
            for (int kk = 0; kk < BKK; kk++) {
                float4 a0 = *(const float4*)&As[kk][ty * 8];
                float4 a1 = *(const float4*)&As[kk][ty * 8 + 4];
                float4 b0 = *(const float4*)&Bs[kk][tx * 8];
                float4 b1 = *(const float4*)&Bs[kk][tx * 8 + 4];
                float ar[8] = {a0.x, a0.y, a0.z, a0.w, a1.x, a1.y, a1.z, a1.w};
                float br[8] = {b0.x, b0.y, b0.z, b0.w, b1.x, b1.y, b1.z, b1.w};
#pragma unroll
                for (int i = 0; i < 8; i++)
#pragma unroll
                    for (int j = 0; j < 8; j++)
                        acc[i][j] = fmaf(ar[i], br[j], acc[i][j]);
            }
            __syncthreads();
        }
    }

    // Epilogue: + b_mix + x residual -> g_U
#pragma unroll
    for (int i = 0; i < 8; i++) {
        const int row = bm + ty * 8 + i;
#pragma unroll
        for (int j4 = 0; j4 < 8; j4 += 4) {
            const int col = bn + tx * 8 + j4;
            float4 xr = *(const float4*)&x[(size_t)row * DDIM + col];
            float4 bb = *(const float4*)&b_mix[col];
            float4 o;
            o.x = acc[i][j4 + 0] + bb.x + xr.x;
            o.y = acc[i][j4 + 1] + bb.y + xr.y;
            o.z = acc[i][j4 + 2] + bb.z + xr.z;
            o.w = acc[i][j4 + 3] + bb.w + xr.w;
            *(float4*)&g_U[(size_t)row * DDIM + col] = o;
        }
    }
}

// ---------------------------------------------------------------------------
// LayerNorm over last dim (256). One 256-thread block per row.
// Device helper; in/out bound to __device__ globals inside device code.
// ---------------------------------------------------------------------------
__device__ __forceinline__ void ln_row(const float* __restrict__ in,
                                       const float* __restrict__ g,
                                       const float* __restrict__ b,
                                       float* __restrict__ out)
{
    const int row = blockIdx.x;
    const int t   = threadIdx.x;
    float v = in[(size_t)row * DDIM + t];

    float s = v;
#pragma unroll
    for (int o = 16; o > 0; o >>= 1) s += __shfl_xor_sync(0xffffffffu, s, o);
    __shared__ float r1[8], r2[8];
    if ((t & 31) == 0) r1[t >> 5] = s;
    __syncthreads();
    float tot = 0.0f;
#pragma unroll
    for (int i = 0; i < 8; i++) tot += r1[i];
    const float mu = tot * (1.0f / 256.0f);

    const float d = v - mu;
    float s2 = d * d;
#pragma unroll
    for (int o = 16; o > 0; o >>= 1) s2 += __shfl_xor_sync(0xffffffffu, s2, o);
    if ((t & 31) == 0) r2[t >> 5] = s2;
    __syncthreads();
    float tv = 0.0f;
#pragma unroll
    for (int i = 0; i < 8; i++) tv += r2[i];
    const float var = tv * (1.0f / 256.0f);

    out[(size_t)row * DDIM + t] = d * rsqrtf(var + 1e-5f) * g[t] + b[t];
}

// LN1: g_U -> g_Hh (globals referenced in device code — valid device addresses)
__global__ void ln1_kernel(const float* __restrict__ g,
                           const float* __restrict__ b)
{
    ln_row(g_U, g, b, g_Hh);
}

// LN2: g_V -> out (out is the harness's d_out, a real device pointer)
__global__ void ln2_kernel(const float* __restrict__ g,
                           const float* __restrict__ b,
                           float* __restrict__ out)
{
    ln_row(g_V, g, b, out);
}

// ---------------------------------------------------------------------------
// Kernel 3: FFN1 = gelu(h @ W1 + b_ff1)   [16384 x 256] @ [256 x 1024]
// Grid: (128, 8), 256 threads.
// ---------------------------------------------------------------------------
__global__ void ffn1_kernel(const float* __restrict__ W1,
                            const float* __restrict__ bff1)
{
    __shared__ float As[BKK][BM];
    __shared__ float Bs[BKK][BN];

    const int tid = threadIdx.x;
    const int bm  = blockIdx.x * BM;
    const int bn  = blockIdx.y * BN;
    const int tx  = tid & 15;
    const int ty  = tid >> 4;
    const int a_row = tid >> 1;
    const int a_col = (tid & 1) * 4;
    const int b_row = tid >> 5;
    const int b_col = (tid & 31) * 4;

    float acc[8][8];
#pragma unroll
    for (int i = 0; i < 8; i++)
#pragma unroll
        for (int j = 0; j < 8; j++) acc[i][j] = 0.0f;

    for (int k0 = 0; k0 < DDIM; k0 += BKK) {
        float4 av = *(const float4*)&g_Hh[(size_t)(bm + a_row) * DDIM + k0 + a_col];
        As[a_col + 0][a_row] = av.x;
        As[a_col + 1][a_row] = av.y;
        As[a_col + 2][a_row] = av.z;
        As[a_col + 3][a_row] = av.w;
        float4 bv = *(const float4*)&W1[(size_t)(k0 + b_row) * HDIM + bn + b_col];
        *(float4*)&Bs[b_row][b_col] = bv;
        __syncthreads();
#pragma unroll
        for (int kk = 0; kk < BKK; kk++) {
            float4 a0 = *(const float4*)&As[kk][ty * 8];
            float4 a1 = *(const float4*)&As[kk][ty * 8 + 4];
            float4 b0 = *(const float4*)&Bs[kk][tx * 8];
            float4 b1 = *(const float4*)&Bs[kk][tx * 8 + 4];
            float ar[8] = {a0.x, a0.y, a0.z, a0.w, a1.x, a1.y, a1.z, a1.w};
            float br[8] = {b0.x, b0.y, b0.z, b0.w, b1.x, b1.y, b1.z, b1.w};
#pragma unroll
            for (int i = 0; i < 8; i++)
#pragma unroll
                for (int j = 0; j < 8; j++)
                    acc[i][j] = fmaf(ar[i], br[j], acc[i][j]);
        }
        __syncthreads();
    }

#pragma unroll
    for (int i = 0; i < 8; i++) {
        const int row = bm + ty * 8 + i;
#pragma unroll
        for (int j4 = 0; j4 < 8; j4 += 4) {
            const int col = bn + tx * 8 + j4;
            float4 bb = *(const float4*)&bff1[col];
            float4 o;
            float vx = acc[i][j4 + 0] + bb.x;
            float vy = acc[i][j4 + 1] + bb.y;
            float vz = acc[i][j4 + 2] + bb.z;
            float vw = acc[i][j4 + 3] + bb.w;
            // exact GELU: 0.5*x*(1+erf(x/sqrt(2)))
            o.x = 0.5f * vx * (1.0f + erff(vx * 0.70710678118654752f));
            o.y = 0.5f * vy * (1.0f + erff(vy * 0.70710678118654752f));
            o.z = 0.5f * vz * (1.0f + erff(vz * 0.70710678118654752f));
            o.w = 0.5f * vw * (1.0f + erff(vw * 0.70710678118654752f));
            *(float4*)&g_Act[(size_t)row * HDIM + col] = o;
        }
    }
}

// ---------------------------------------------------------------------------
// Kernel 4: FFN2 = Act @ W2 + b_ff2 + h   [16384 x 1024] @ [1024 x 256]
// Grid: (128, 2), 256 threads.
// ---------------------------------------------------------------------------
__global__ void ffn2_kernel(const float* __restrict__ W2,
                            const float* __restrict__ bff2)
{
    __shared__ float As[BKK][BM];
    __shared__ float Bs[BKK][BN];

    const int tid = threadIdx.x;
    const int bm  = blockIdx.x * BM;
    const int bn  = blockIdx.y * BN;
    const int tx  = tid & 15;
    const int ty  = tid >> 4;
    const int a_row = tid >> 1;
    const int a_col = (tid & 1) * 4;
    const int b_row = tid >> 5;
    const int b_col = (tid & 31) * 4;

    float acc[8][8];
#pragma unroll
    for (int i = 0; i < 8; i++)
#pragma unroll
        for (int j = 0; j < 8; j++) acc[i][j] = 0.0f;

    for (int k0 = 0; k0 < HDIM; k0 += BKK) {
        float4 av = *(const float4*)&g_Act[(size_t)(bm + a_row) * HDIM + k0 + a_col];
        As[a_col + 0][a_row] = av.x;
        As[a_col + 1][a_row] = av.y;
        As[a_col + 2][a_row] = av.z;
        As[a_col + 3][a_row] = av.w;
        float4 bv = *(const float4*)&W2[(size_t)(k0 + b_row) * DDIM + bn + b_col];
        *(float4*)&Bs[b_row][b_col] = bv;
        __syncthreads();
#pragma unroll
        for (int kk = 0; kk < BKK; kk++) {
            float4 a0 = *(const float4*)&As[kk][ty * 8];
            float4 a1 = *(const float4*)&As[kk][ty * 8 + 4];
            float4 b0 = *(const float4*)&Bs[kk][tx * 8];
            float4 b1 = *(const float4*)&Bs[kk][tx * 8 + 4];
            float ar[8] = {a0.x, a0.y, a0.z, a0.w, a1.x, a1.y, a1.z, a1.w};
            float br[8] = {b0.x, b0.y, b0.z, b0.w, b1.x, b1.y, b1.z, b1.w};
#pragma unroll
            for (int i = 0; i < 8; i++)
#pragma unroll
                for (int j = 0; j < 8; j++)
                    acc[i][j] = fmaf(ar[i], br[j], acc[i][j]);
        }
        __syncthreads();
    }

    // Epilogue: + b_ff2 + h residual -> g_V
#pragma unroll
    for (int i = 0; i < 8; i++) {
        const int row = bm + ty * 8 + i;
#pragma unroll
        for (int j4 = 0; j4 < 8; j4 += 4) {
            const int col = bn + tx * 8 + j4;
            float4 hr = *(const float4*)&g_Hh[(size_t)row * DDIM + col];
            float4 bb = *(const float4*)&bff2[col];
            float4 o;
            o.x = acc[i][j4 + 0] + bb.x + hr.x;
            o.y = acc[i][j4 + 1] + bb.y + hr.y;
            o.z = acc[i][j4 + 2] + bb.z + hr.z;
            o.w = acc[i][j4 + 3] + bb.w + hr.w;
            *(float4*)&g_V[(size_t)row * DDIM + col] = o;
        }
    }
}

// ---------------------------------------------------------------------------
extern "C" void kernel_launch(void* const* d_in, const int* in_sizes, int n_in,
                              void* d_out, int out_size)
{
    const float* x     = (const float*)d_in[0];
    const float* w_mix = (const float*)d_in[1];
    const float* b_mix = (const float*)d_in[2];
    const float* g1    = (const float*)d_in[3];
    const float* b1    = (const float*)d_in[4];
    const float* w_ff1 = (const float*)d_in[5];
    const float* b_ff1 = (const float*)d_in[6];
    const float* w_ff2 = (const float*)d_in[7];
    const float* b_ff2 = (const float*)d_in[8];
    const float* g2    = (const float*)d_in[9];
    const float* b2    = (const float*)d_in[10];
    float* out = (float*)d_out;

    dim3 block(256);

    // 1) mix conv-GEMM + residual -> g_U
    mix_gemm_kernel<<<dim3(MROWS / BM, DDIM / BN), block>>>(x, w_mix, b_mix);
    // 2) LN1: g_U -> g_Hh
    ln1_kernel<<<MROWS, 256>>>(g1, b1);
    // 3) FFN1 + GELU -> g_Act
    ffn1_kernel<<<dim3(MROWS / BM, HDIM / BN), block>>>(w_ff1, b_ff1);
    // 4) FFN2 + residual -> g_V
    ffn2_kernel<<<dim3(MROWS / BM, DDIM / BN), block>>>(w_ff2, b_ff2);
    // 5) LN2: g_V -> out
    ln2_kernel<<<MROWS, 256>>>(g2, b2, out);
}

// round 7
// speedup vs baseline: 2.5958x; 2.5861x over previous
#include <cuda_runtime.h>
#include <math.h>

// Problem constants
#define BATCH 4
#define SEQ   4096
#define DDIM  256
#define HDIM  1024
#define TAPS  15
#define MROWS (BATCH*SEQ)   // 16384

// GEMM tile config (tensor core)
#define BM 128
#define BN 128
#define BK 16
#define AKP 20              // A smem row stride in words (BK + 4 pad)
#define BNP 136             // B smem row stride in words (BN + 8 pad)

// Scratch (static device globals; referenced ONLY from device code — passing
// them as kernel args from host passes the host shadow address on GB300/ATS).
__device__ float g_U  [MROWS * DDIM];
__device__ float g_Hh [MROWS * DDIM];
__device__ float g_Act[MROWS * HDIM];
__device__ float g_V  [MROWS * DDIM];

// ---------------------------------------------------------------------------
// tf32 helpers
// ---------------------------------------------------------------------------
__device__ __forceinline__ unsigned f2tf(float x) {
    unsigned u;
    asm("cvt.rna.tf32.f32 %0, %1;" : "=r"(u) : "f"(x));
    return u;
}

__device__ __forceinline__ void mma8(float c[4], const unsigned a[4], const unsigned b[2]) {
    asm volatile(
        "mma.sync.aligned.m16n8k8.row.col.f32.tf32.tf32.f32 "
        "{%0,%1,%2,%3}, {%4,%5,%6,%7}, {%8,%9}, {%0,%1,%2,%3};\n"
        : "+f"(c[0]), "+f"(c[1]), "+f"(c[2]), "+f"(c[3])
        : "r"(a[0]), "r"(a[1]), "r"(a[2]), "r"(a[3]), "r"(b[0]), "r"(b[1]));
}

// Compute one BK=16 slice from smem buffer s into acc.
// Warp layout: 8 warps = 2(m) x 4(n); warp tile 64x32 = 4x4 m16n8k8 frags.
__device__ __forceinline__ void compute_slice(const unsigned* __restrict__ Asb,
                                              const unsigned* __restrict__ Bsb,
                                              int m_w, int n_w, int lane,
                                              float acc[4][4][4])
{
    const int r  = lane >> 2;
    const int kq = lane & 3;
#pragma unroll
    for (int ks = 0; ks < 2; ks++) {
        unsigned af[4][4], bf[4][2];
#pragma unroll
        for (int mi = 0; mi < 4; mi++) {
            const int row = m_w + mi * 16 + r;
            af[mi][0] = Asb[row * AKP + ks * 8 + kq];
            af[mi][1] = Asb[(row + 8) * AKP + ks * 8 + kq];
            af[mi][2] = Asb[row * AKP + ks * 8 + kq + 4];
            af[mi][3] = Asb[(row + 8) * AKP + ks * 8 + kq + 4];
        }
#pragma unroll
        for (int ni = 0; ni < 4; ni++) {
            const int n = n_w + ni * 8 + r;
            bf[ni][0] = Bsb[(ks * 8 + kq) * BNP + n];
            bf[ni][1] = Bsb[(ks * 8 + kq + 4) * BNP + n];
        }
#pragma unroll
        for (int mi = 0; mi < 4; mi++)
#pragma unroll
            for (int ni = 0; ni < 4; ni++)
                mma8(acc[mi][ni], af[mi], bf[ni]);
    }
}

__device__ __forceinline__ void store_tiles(unsigned* __restrict__ Asb,
                                            unsigned* __restrict__ Bsb,
                                            int am, int ak0, int bk, int bn0,
                                            const float4& pA0, const float4& pA1,
                                            const float4& pB0, const float4& pB1)
{
    unsigned* a = &Asb[am * AKP + ak0];
    a[0] = f2tf(pA0.x); a[1] = f2tf(pA0.y); a[2] = f2tf(pA0.z); a[3] = f2tf(pA0.w);
    a[4] = f2tf(pA1.x); a[5] = f2tf(pA1.y); a[6] = f2tf(pA1.z); a[7] = f2tf(pA1.w);
    unsigned* b = &Bsb[bk * BNP + bn0];
    b[0] = f2tf(pB0.x); b[1] = f2tf(pB0.y); b[2] = f2tf(pB0.z); b[3] = f2tf(pB0.w);
    b[4] = f2tf(pB1.x); b[5] = f2tf(pB1.y); b[6] = f2tf(pB1.z); b[7] = f2tf(pB1.w);
}

// ---------------------------------------------------------------------------
// Kernel 1: mix GEMM (causal local conv, im2col) + bias + residual -> g_U
// M=16384, K=15*256, N=256. Grid (128, 2), 256 threads.
// ---------------------------------------------------------------------------
__global__ void __launch_bounds__(256) mix_gemm_tc(const float* __restrict__ x,
                                                   const float* __restrict__ w_mix,
                                                   const float* __restrict__ b_mix)
{
    __shared__ unsigned As[2][BM * AKP];
    __shared__ unsigned Bs[2][BK * BNP];

    const int tid  = threadIdx.x;
    const int lane = tid & 31, wid = tid >> 5;
    const int bm = blockIdx.x * BM, bn = blockIdx.y * BN;
    const int m_w = (wid >> 2) * 64, n_w = (wid & 3) * 32;

    const int bidx = bm / SEQ, n_base = bm % SEQ;
    const float* xb = x + (size_t)bidx * SEQ * DDIM;

    // load mappings
    const int am = tid >> 1, ak0 = (tid & 1) * 8;   // A: row, k-offset
    const int bk = tid >> 4, bn0 = (tid & 15) * 8;  // B: k-row, n-offset

    float acc[4][4][4];
#pragma unroll
    for (int i = 0; i < 4; i++)
#pragma unroll
        for (int j = 0; j < 4; j++)
#pragma unroll
            for (int q = 0; q < 4; q++) acc[i][j][q] = 0.0f;

    const int NIT = TAPS * (DDIM / BK);  // 240
    float4 pA0, pA1, pB0, pB1;

    auto prefetch = [&](int it) {
        const int tap = it >> 4;
        const int d0  = (it & 15) << 4;
        const int src = n_base + am + tap - 14;
        if (src >= 0) {
            const float* p = &xb[(size_t)src * DDIM + d0 + ak0];
            pA0 = *(const float4*)p;
            pA1 = *(const float4*)(p + 4);
        } else {
            pA0 = make_float4(0.f, 0.f, 0.f, 0.f);
            pA1 = pA0;
        }
        const float* w = w_mix + (size_t)tap * DDIM * DDIM + (size_t)(d0 + bk) * DDIM + bn + bn0;
        pB0 = *(const float4*)w;
        pB1 = *(const float4*)(w + 4);
    };

    prefetch(0);
    for (int it = 0; it < NIT; ++it) {
        const int s = it & 1;
        store_tiles(As[s], Bs[s], am, ak0, bk, bn0, pA0, pA1, pB0, pB1);
        __syncthreads();
        if (it + 1 < NIT) prefetch(it + 1);
        compute_slice(As[s], Bs[s], m_w, n_w, lane, acc);
    }

    // epilogue: + b_mix + x residual -> g_U
#pragma unroll
    for (int mi = 0; mi < 4; mi++) {
        const int r0 = bm + m_w + mi * 16 + (lane >> 2);
#pragma unroll
        for (int ni = 0; ni < 4; ni++) {
            const int c = bn + n_w + ni * 8 + 2 * (lane & 3);
            float2 bb = *(const float2*)&b_mix[c];
            float2 x0 = *(const float2*)&x[(size_t)r0 * DDIM + c];
            float2 x1 = *(const float2*)&x[(size_t)(r0 + 8) * DDIM + c];
            float2 o0 = { acc[mi][ni][0] + bb.x + x0.x, acc[mi][ni][1] + bb.y + x0.y };
            float2 o1 = { acc[mi][ni][2] + bb.x + x1.x, acc[mi][ni][3] + bb.y + x1.y };
            *(float2*)&g_U[(size_t)r0 * DDIM + c] = o0;
            *(float2*)&g_U[(size_t)(r0 + 8) * DDIM + c] = o1;
        }
    }
}

// ---------------------------------------------------------------------------
// Kernel 3: FFN1 = gelu(h @ W1 + b_ff1). M=16384, K=256, N=1024. Grid (128, 8).
// ---------------------------------------------------------------------------
__global__ void __launch_bounds__(256) ffn1_tc(const float* __restrict__ W1,
                                               const float* __restrict__ bff1)
{
    __shared__ unsigned As[2][BM * AKP];
    __shared__ unsigned Bs[2][BK * BNP];

    const int tid  = threadIdx.x;
    const int lane = tid & 31, wid = tid >> 5;
    const int bm = blockIdx.x * BM, bn = blockIdx.y * BN;
    const int m_w = (wid >> 2) * 64, n_w = (wid & 3) * 32;

    const int am = tid >> 1, ak0 = (tid & 1) * 8;
    const int bk = tid >> 4, bn0 = (tid & 15) * 8;

    float acc[4][4][4];
#pragma unroll
    for (int i = 0; i < 4; i++)
#pragma unroll
        for (int j = 0; j < 4; j++)
#pragma unroll
            for (int q = 0; q < 4; q++) acc[i][j][q] = 0.0f;

    const int NIT = DDIM / BK;  // 16
    float4 pA0, pA1, pB0, pB1;

    auto prefetch = [&](int it) {
        const int k0 = it << 4;
        const float* p = &g_Hh[(size_t)(bm + am) * DDIM + k0 + ak0];
        pA0 = *(const float4*)p;
        pA1 = *(const float4*)(p + 4);
        const float* w = &W1[(size_t)(k0 + bk) * HDIM + bn + bn0];
        pB0 = *(const float4*)w;
        pB1 = *(const float4*)(w + 4);
    };

    prefetch(0);
    for (int it = 0; it < NIT; ++it) {
        const int s = it & 1;
        store_tiles(As[s], Bs[s], am, ak0, bk, bn0, pA0, pA1, pB0, pB1);
        __syncthreads();
        if (it + 1 < NIT) prefetch(it + 1);
        compute_slice(As[s], Bs[s], m_w, n_w, lane, acc);
    }

    const float kInvSqrt2 = 0.70710678118654752f;
#pragma unroll
    for (int mi = 0; mi < 4; mi++) {
        const int r0 = bm + m_w + mi * 16 + (lane >> 2);
#pragma unroll
        for (int ni = 0; ni < 4; ni++) {
            const int c = bn + n_w + ni * 8 + 2 * (lane & 3);
            float2 bb = *(const float2*)&bff1[c];
            float v00 = acc[mi][ni][0] + bb.x;
            float v01 = acc[mi][ni][1] + bb.y;
            float v10 = acc[mi][ni][2] + bb.x;
            float v11 = acc[mi][ni][3] + bb.y;
            float2 o0 = { 0.5f * v00 * (1.0f + erff(v00 * kInvSqrt2)),
                          0.5f * v01 * (1.0f + erff(v01 * kInvSqrt2)) };
            float2 o1 = { 0.5f * v10 * (1.0f + erff(v10 * kInvSqrt2)),
                          0.5f * v11 * (1.0f + erff(v11 * kInvSqrt2)) };
            *(float2*)&g_Act[(size_t)r0 * HDIM + c] = o0;
            *(float2*)&g_Act[(size_t)(r0 + 8) * HDIM + c] = o1;
        }
    }
}

// ---------------------------------------------------------------------------
// Kernel 4: FFN2 = Act @ W2 + b_ff2 + h. M=16384, K=1024, N=256. Grid (128, 2).
// ---------------------------------------------------------------------------
__global__ void __launch_bounds__(256) ffn2_tc(const float* __restrict__ W2,
                                               const float* __restrict__ bff2)
{
    __shared__ unsigned As[2][BM * AKP];
    __shared__ unsigned Bs[2][BK * BNP];

    const int tid  = threadIdx.x;
    const int lane = tid & 31, wid = tid >> 5;
    const int bm = blockIdx.x * BM, bn = blockIdx.y * BN;
    const int m_w = (wid >> 2) * 64, n_w = (wid & 3) * 32;

    const int am = tid >> 1, ak0 = (tid & 1) * 8;
    const int bk = tid >> 4, bn0 = (tid & 15) * 8;

    float acc[4][4][4];
#pragma unroll
    for (int i = 0; i < 4; i++)
#pragma unroll
        for (int j = 0; j < 4; j++)
#pragma unroll
            for (int q = 0; q < 4; q++) acc[i][j][q] = 0.0f;

    const int NIT = HDIM / BK;  // 64
    float4 pA0, pA1, pB0, pB1;

    auto prefetch = [&](int it) {
        const int k0 = it << 4;
        const float* p = &g_Act[(size_t)(bm + am) * HDIM + k0 + ak0];
        pA0 = *(const float4*)p;
        pA1 = *(const float4*)(p + 4);
        const float* w = &W2[(size_t)(k0 + bk) * DDIM + bn + bn0];
        pB0 = *(const float4*)w;
        pB1 = *(const float4*)(w + 4);
    };

    prefetch(0);
    for (int it = 0; it < NIT; ++it) {
        const int s = it & 1;
        store_tiles(As[s], Bs[s], am, ak0, bk, bn0, pA0, pA1, pB0, pB1);
        __syncthreads();
        if (it + 1 < NIT) prefetch(it + 1);
        compute_slice(As[s], Bs[s], m_w, n_w, lane, acc);
    }

    // epilogue: + b_ff2 + h residual -> g_V
#pragma unroll
    for (int mi = 0; mi < 4; mi++) {
        const int r0 = bm + m_w + mi * 16 + (lane >> 2);
#pragma unroll
        for (int ni = 0; ni < 4; ni++) {
            const int c = bn + n_w + ni * 8 + 2 * (lane & 3);
            float2 bb = *(const float2*)&bff2[c];
            float2 h0 = *(const float2*)&g_Hh[(size_t)r0 * DDIM + c];
            float2 h1 = *(const float2*)&g_Hh[(size_t)(r0 + 8) * DDIM + c];
            float2 o0 = { acc[mi][ni][0] + bb.x + h0.x, acc[mi][ni][1] + bb.y + h0.y };
            float2 o1 = { acc[mi][ni][2] + bb.x + h1.x, acc[mi][ni][3] + bb.y + h1.y };
            *(float2*)&g_V[(size_t)r0 * DDIM + c] = o0;
            *(float2*)&g_V[(size_t)(r0 + 8) * DDIM + c] = o1;
        }
    }
}

// ---------------------------------------------------------------------------
// LayerNorm over last dim (256). One 256-thread block per row.
// ---------------------------------------------------------------------------
__device__ __forceinline__ void ln_row(const float* __restrict__ in,
                                       const float* __restrict__ g,
                                       const float* __restrict__ b,
                                       float* __restrict__ out)
{
    const int row = blockIdx.x;
    const int t   = threadIdx.x;
    float v = in[(size_t)row * DDIM + t];

    float s = v;
#pragma unroll
    for (int o = 16; o > 0; o >>= 1) s += __shfl_xor_sync(0xffffffffu, s, o);
    __shared__ float r1[8], r2[8];
    if ((t & 31) == 0) r1[t >> 5] = s;
    __syncthreads();
    float tot = 0.0f;
#pragma unroll
    for (int i = 0; i < 8; i++) tot += r1[i];
    const float mu = tot * (1.0f / 256.0f);

    const float d = v - mu;
    float s2 = d * d;
#pragma unroll
    for (int o = 16; o > 0; o >>= 1) s2 += __shfl_xor_sync(0xffffffffu, s2, o);
    if ((t & 31) == 0) r2[t >> 5] = s2;
    __syncthreads();
    float tv = 0.0f;
#pragma unroll
    for (int i = 0; i < 8; i++) tv += r2[i];
    const float var = tv * (1.0f / 256.0f);

    out[(size_t)row * DDIM + t] = d * rsqrtf(var + 1e-5f) * g[t] + b[t];
}

__global__ void ln1_kernel(const float* __restrict__ g, const float* __restrict__ b)
{
    ln_row(g_U, g, b, g_Hh);
}

__global__ void ln2_kernel(const float* __restrict__ g, const float* __restrict__ b,
                           float* __restrict__ out)
{
    ln_row(g_V, g, b, out);
}

// ---------------------------------------------------------------------------
extern "C" void kernel_launch(void* const* d_in, const int* in_sizes, int n_in,
                              void* d_out, int out_size)
{
    const float* x     = (const float*)d_in[0];
    const float* w_mix = (const float*)d_in[1];
    const float* b_mix = (const float*)d_in[2];
    const float* g1    = (const float*)d_in[3];
    const float* b1    = (const float*)d_in[4];
    const float* w_ff1 = (const float*)d_in[5];
    const float* b_ff1 = (const float*)d_in[6];
    const float* w_ff2 = (const float*)d_in[7];
    const float* b_ff2 = (const float*)d_in[8];
    const float* g2    = (const float*)d_in[9];
    const float* b2    = (const float*)d_in[10];
    float* out = (float*)d_out;

    dim3 block(256);

    mix_gemm_tc<<<dim3(MROWS / BM, DDIM / BN), block>>>(x, w_mix, b_mix);
    ln1_kernel<<<MROWS, 256>>>(g1, b1);
    ffn1_tc<<<dim3(MROWS / BM, HDIM / BN), block>>>(w_ff1, b_ff1);
    ffn2_tc<<<dim3(MROWS / BM, DDIM / BN), block>>>(w_ff2, b_ff2);
    ln2_kernel<<<MROWS, 256>>>(g2, b2, out);
}

// round 10
// speedup vs baseline: 3.1587x; 1.2169x over previous
#include <cuda_runtime.h>
#include <math.h>

// Problem constants
#define BATCH 4
#define SEQ   4096
#define DDIM  256
#define HDIM  1024
#define TAPS  15
#define MROWS (BATCH*SEQ)   // 16384

// Tile config
#define BM 128
#define BN 128
#define BK 16
#define STAGES 3
#define AWORDS (BM*BK)      // 2048 words / stage (8KB)
#define BWORDS (BK*BN)      // 2048 words / stage (8KB)

// Scratch (device globals; referenced ONLY from device code — host-passing
// them gives the host shadow address on GB300/ATS).
__device__ float g_U  [MROWS * DDIM];
__device__ float g_Hh [MROWS * DDIM];
__device__ float g_Act[MROWS * HDIM];
__device__ float g_V  [MROWS * DDIM];

// ---------------------------------------------------------------------------
// cp.async helpers
// ---------------------------------------------------------------------------
__device__ __forceinline__ unsigned smem_u32p(const void* p) {
    return (unsigned)__cvta_generic_to_shared(p);
}
__device__ __forceinline__ void cp16(unsigned dst, const float* src) {
    asm volatile("cp.async.cg.shared.global [%0], [%1], 16;" :: "r"(dst), "l"(src));
}
__device__ __forceinline__ void cp16z(unsigned dst, const float* src, int sb) {
    asm volatile("cp.async.cg.shared.global [%0], [%1], 16, %2;" :: "r"(dst), "l"(src), "r"(sb));
}
#define CP_COMMIT() asm volatile("cp.async.commit_group;")
#define CP_WAIT1()  asm volatile("cp.async.wait_group 1;")

__device__ __forceinline__ void mma8(float c[4], const unsigned a[4], const unsigned b[2]) {
    asm volatile(
        "mma.sync.aligned.m16n8k8.row.col.f32.tf32.tf32.f32 "
        "{%0,%1,%2,%3}, {%4,%5,%6,%7}, {%8,%9}, {%0,%1,%2,%3};\n"
        : "+f"(c[0]), "+f"(c[1]), "+f"(c[2]), "+f"(c[3])
        : "r"(a[0]), "r"(a[1]), "r"(a[2]), "r"(a[3]), "r"(b[0]), "r"(b[1]));
}

// ---------------------------------------------------------------------------
// Swizzled-layout compute of one BK=16 slice.
// A layout: word = row*16 + (((k>>2) ^ ((row>>1)&3))<<2) + (k&3).
// B layout: word = k*128 + (n ^ (8*(k&3))).
// Both conflict-free for the m16n8k8 fragment pattern (bank math verified:
// A: 16*(r&1) + 4*(c^cx(r)) + kq covers all 32 banks; B: (8ni+r)^(8kq) ditto).
// Warp layout: 8 warps = 2(m) x 4(n); warp tile 64x32 = 4x4 m16n8k8 frags.
// ---------------------------------------------------------------------------
__device__ __forceinline__ void compute_slice(const float* __restrict__ Asb,
                                              const float* __restrict__ Bsb,
                                              int m_w, int n_w, int lane,
                                              float acc[4][4][4])
{
    const int r  = lane >> 2;
    const int kq = lane & 3;
    const int cx = (r >> 1) & 3;               // A chunk xor (row-derived, invariant)
    const unsigned* A = (const unsigned*)Asb;
    const unsigned* B = (const unsigned*)Bsb;

#pragma unroll
    for (int ks = 0; ks < 2; ks++) {
        const int k0 = (((2 * ks + 0) ^ cx) << 2) + kq;   // j=0 word offset in row
        const int k1 = (((2 * ks + 1) ^ cx) << 2) + kq;   // j=1
        unsigned af[4][4], bf[4][2];
#pragma unroll
        for (int mi = 0; mi < 4; mi++) {
            const int row = m_w + mi * 16 + r;
            af[mi][0] = A[row * 16 + k0];
            af[mi][1] = A[(row + 8) * 16 + k0];
            af[mi][2] = A[row * 16 + k1];
            af[mi][3] = A[(row + 8) * 16 + k1];
        }
        const int kb0 = (8 * ks + kq) * 128;
        const int kb1 = (8 * ks + kq + 4) * 128;
#pragma unroll
        for (int ni = 0; ni < 4; ni++) {
            const int n = (n_w + ni * 8 + r) ^ (8 * kq);
            bf[ni][0] = B[kb0 + n];
            bf[ni][1] = B[kb1 + n];
        }
#pragma unroll
        for (int mi = 0; mi < 4; mi++)
#pragma unroll
            for (int ni = 0; ni < 4; ni++)
                mma8(acc[mi][ni], af[mi], bf[ni]);
    }
}

// Per-thread swizzled STS destinations. Each thread owns two ADJACENT logical
// 16B chunks (cn0, cn0+1). Swizzled slots are (cn0^X) and (cn0^X)^1 — the
// second chunk address is first ^ 16 BYTES (bit-4 flip), NOT first + 16.
// (R9 bug: +16 is wrong whenever X is odd, and overflows into the next row.)
__device__ __forceinline__ unsigned a_sts_base(const float* As0, int am, int ak0) {
    const int c0 = (ak0 >> 2) ^ ((am >> 1) & 3);
    return smem_u32p(As0 + am * 16 + (c0 << 2));
}
__device__ __forceinline__ unsigned b_sts_base(const float* Bs0, int bk, int bn0) {
    const int c0 = (bn0 >> 2) ^ (2 * (bk & 3));
    return smem_u32p(Bs0 + bk * 128 + (c0 << 2));
}

// ---------------------------------------------------------------------------
// Kernel 1: mix GEMM (causal local conv, im2col) + bias + residual -> g_U
// M=16384, K=15*256, N=256. Grid (128, 2), 256 threads.
// ---------------------------------------------------------------------------
__global__ void __launch_bounds__(256) mix_gemm_tc(const float* __restrict__ x,
                                                   const float* __restrict__ w_mix,
                                                   const float* __restrict__ b_mix)
{
    __shared__ __align__(128) float As[STAGES][AWORDS];
    __shared__ __align__(128) float Bs[STAGES][BWORDS];

    const int tid  = threadIdx.x;
    const int lane = tid & 31, wid = tid >> 5;
    const int bm = blockIdx.x * BM, bn = blockIdx.y * BN;
    const int m_w = (wid >> 2) * 64, n_w = (wid & 3) * 32;

    const int bidx = bm / SEQ, n_base = bm % SEQ;
    const float* xb = x + (size_t)bidx * SEQ * DDIM;

    const int am = tid >> 1, ak0 = (tid & 1) * 8;
    const int bk = tid >> 4, bn0 = (tid & 15) * 8;
    const unsigned aDst = a_sts_base(As[0], am, ak0);
    const unsigned bDst = b_sts_base(Bs[0], bk, bn0);

    float acc[4][4][4];
#pragma unroll
    for (int i = 0; i < 4; i++)
#pragma unroll
        for (int j = 0; j < 4; j++)
#pragma unroll
            for (int q = 0; q < 4; q++) acc[i][j][q] = 0.0f;

    const int NIT = TAPS * (DDIM / BK);  // 240

    auto issue_load = [&](int it, int s) {
        const int tap = it >> 4;
        const int d0  = (it & 15) << 4;
        const int src = n_base + am + tap - 14;
        const int sb  = (src >= 0) ? 16 : 0;
        const float* gA = &xb[(size_t)(src >= 0 ? src : 0) * DDIM + d0 + ak0];
        const unsigned a = aDst + (unsigned)s * (AWORDS * 4);
        cp16z(a,       gA,     sb);
        cp16z(a ^ 16u, gA + 4, sb);
        const float* gB = w_mix + ((size_t)tap * DDIM + (d0 + bk)) * DDIM + bn + bn0;
        const unsigned b = bDst + (unsigned)s * (BWORDS * 4);
        cp16(b,       gB);
        cp16(b ^ 16u, gB + 4);
        CP_COMMIT();
    };

    for (int s = 0; s < STAGES - 1; s++) issue_load(s, s);
    for (int it = 0; it < NIT; ++it) {
        CP_WAIT1();
        __syncthreads();
        const int nxt = it + STAGES - 1;
        if (nxt < NIT) issue_load(nxt, nxt % STAGES);
        else CP_COMMIT();
        compute_slice(As[it % STAGES], Bs[it % STAGES], m_w, n_w, lane, acc);
    }

    // epilogue: + b_mix + x residual -> g_U
#pragma unroll
    for (int mi = 0; mi < 4; mi++) {
        const int r0 = bm + m_w + mi * 16 + (lane >> 2);
#pragma unroll
        for (int ni = 0; ni < 4; ni++) {
            const int c = bn + n_w + ni * 8 + 2 * (lane & 3);
            float2 bb = *(const float2*)&b_mix[c];
            float2 x0 = *(const float2*)&x[(size_t)r0 * DDIM + c];
            float2 x1 = *(const float2*)&x[(size_t)(r0 + 8) * DDIM + c];
            float2 o0 = { acc[mi][ni][0] + bb.x + x0.x, acc[mi][ni][1] + bb.y + x0.y };
            float2 o1 = { acc[mi][ni][2] + bb.x + x1.x, acc[mi][ni][3] + bb.y + x1.y };
            *(float2*)&g_U[(size_t)r0 * DDIM + c] = o0;
            *(float2*)&g_U[(size_t)(r0 + 8) * DDIM + c] = o1;
        }
    }
}

// ---------------------------------------------------------------------------
// Kernel 3: FFN1 = gelu(h @ W1 + b_ff1). M=16384, K=256, N=1024. Grid (128, 8).
// ---------------------------------------------------------------------------
__global__ void __launch_bounds__(256) ffn1_tc(const float* __restrict__ W1,
                                               const float* __restrict__ bff1)
{
    __shared__ __align__(128) float As[STAGES][AWORDS];
    __shared__ __align__(128) float Bs[STAGES][BWORDS];

    const int tid  = threadIdx.x;
    const int lane = tid & 31, wid = tid >> 5;
    const int bm = blockIdx.x * BM, bn = blockIdx.y * BN;
    const int m_w = (wid >> 2) * 64, n_w = (wid & 3) * 32;

    const int am = tid >> 1, ak0 = (tid & 1) * 8;
    const int bk = tid >> 4, bn0 = (tid & 15) * 8;
    const unsigned aDst = a_sts_base(As[0], am, ak0);
    const unsigned bDst = b_sts_base(Bs[0], bk, bn0);

    float acc[4][4][4];
#pragma unroll
    for (int i = 0; i < 4; i++)
#pragma unroll
        for (int j = 0; j < 4; j++)
#pragma unroll
            for (int q = 0; q < 4; q++) acc[i][j][q] = 0.0f;

    const int NIT = DDIM / BK;  // 16

    auto issue_load = [&](int it, int s) {
        const int k0 = it << 4;
        const float* gA = &g_Hh[(size_t)(bm + am) * DDIM + k0 + ak0];
        const unsigned a = aDst + (unsigned)s * (AWORDS * 4);
        cp16(a,       gA);
        cp16(a ^ 16u, gA + 4);
        const float* gB = &W1[(size_t)(k0 + bk) * HDIM + bn + bn0];
        const unsigned b = bDst + (unsigned)s * (BWORDS * 4);
        cp16(b,       gB);
        cp16(b ^ 16u, gB + 4);
        CP_COMMIT();
    };

    for (int s = 0; s < STAGES - 1; s++) issue_load(s, s);
    for (int it = 0; it < NIT; ++it) {
        CP_WAIT1();
        __syncthreads();
        const int nxt = it + STAGES - 1;
        if (nxt < NIT) issue_load(nxt, nxt % STAGES);
        else CP_COMMIT();
        compute_slice(As[it % STAGES], Bs[it % STAGES], m_w, n_w, lane, acc);
    }

    const float kInvSqrt2 = 0.70710678118654752f;
#pragma unroll
    for (int mi = 0; mi < 4; mi++) {
        const int r0 = bm + m_w + mi * 16 + (lane >> 2);
#pragma unroll
        for (int ni = 0; ni < 4; ni++) {
            const int c = bn + n_w + ni * 8 + 2 * (lane & 3);
            float2 bb = *(const float2*)&bff1[c];
            float v00 = acc[mi][ni][0] + bb.x;
            float v01 = acc[mi][ni][1] + bb.y;
            float v10 = acc[mi][ni][2] + bb.x;
            float v11 = acc[mi][ni][3] + bb.y;
            float2 o0 = { 0.5f * v00 * (1.0f + erff(v00 * kInvSqrt2)),
                          0.5f * v01 * (1.0f + erff(v01 * kInvSqrt2)) };
            float2 o1 = { 0.5f * v10 * (1.0f + erff(v10 * kInvSqrt2)),
                          0.5f * v11 * (1.0f + erff(v11 * kInvSqrt2)) };
            *(float2*)&g_Act[(size_t)r0 * HDIM + c] = o0;
            *(float2*)&g_Act[(size_t)(r0 + 8) * HDIM + c] = o1;
        }
    }
}

// ---------------------------------------------------------------------------
// Kernel 4: FFN2 = Act @ W2 + b_ff2 + h. M=16384, K=1024, N=256. Grid (128, 2).
// ---------------------------------------------------------------------------
__global__ void __launch_bounds__(256) ffn2_tc(const float* __restrict__ W2,
                                               const float* __restrict__ bff2)
{
    __shared__ __align__(128) float As[STAGES][AWORDS];
    __shared__ __align__(128) float Bs[STAGES][BWORDS];

    const int tid  = threadIdx.x;
    const int lane = tid & 31, wid = tid >> 5;
    const int bm = blockIdx.x * BM, bn = blockIdx.y * BN;
    const int m_w = (wid >> 2) * 64, n_w = (wid & 3) * 32;

    const int am = tid >> 1, ak0 = (tid & 1) * 8;
    const int bk = tid >> 4, bn0 = (tid & 15) * 8;
    const unsigned aDst = a_sts_base(As[0], am, ak0);
    const unsigned bDst = b_sts_base(Bs[0], bk, bn0);

    float acc[4][4][4];
#pragma unroll
    for (int i = 0; i < 4; i++)
#pragma unroll
        for (int j = 0; j < 4; j++)
#pragma unroll
            for (int q = 0; q < 4; q++) acc[i][j][q] = 0.0f;

    const int NIT = HDIM / BK;  // 64

    auto issue_load = [&](int it, int s) {
        const int k0 = it << 4;
        const float* gA = &g_Act[(size_t)(bm + am) * HDIM + k0 + ak0];
        const unsigned a = aDst + (unsigned)s * (AWORDS * 4);
        cp16(a,       gA);
        cp16(a ^ 16u, gA + 4);
        const float* gB = &W2[(size_t)(k0 + bk) * DDIM + bn + bn0];
        const unsigned b = bDst + (unsigned)s * (BWORDS * 4);
        cp16(b,       gB);
        cp16(b ^ 16u, gB + 4);
        CP_COMMIT();
    };

    for (int s = 0; s < STAGES - 1; s++) issue_load(s, s);
    for (int it = 0; it < NIT; ++it) {
        CP_WAIT1();
        __syncthreads();
        const int nxt = it + STAGES - 1;
        if (nxt < NIT) issue_load(nxt, nxt % STAGES);
        else CP_COMMIT();
        compute_slice(As[it % STAGES], Bs[it % STAGES], m_w, n_w, lane, acc);
    }

    // epilogue: + b_ff2 + h residual -> g_V
#pragma unroll
    for (int mi = 0; mi < 4; mi++) {
        const int r0 = bm + m_w + mi * 16 + (lane >> 2);
#pragma unroll
        for (int ni = 0; ni < 4; ni++) {
            const int c = bn + n_w + ni * 8 + 2 * (lane & 3);
            float2 bb = *(const float2*)&bff2[c];
            float2 h0 = *(const float2*)&g_Hh[(size_t)r0 * DDIM + c];
            float2 h1 = *(const float2*)&g_Hh[(size_t)(r0 + 8) * DDIM + c];
            float2 o0 = { acc[mi][ni][0] + bb.x + h0.x, acc[mi][ni][1] + bb.y + h0.y };
            float2 o1 = { acc[mi][ni][2] + bb.x + h1.x, acc[mi][ni][3] + bb.y + h1.y };
            *(float2*)&g_V[(size_t)r0 * DDIM + c] = o0;
            *(float2*)&g_V[(size_t)(r0 + 8) * DDIM + c] = o1;
        }
    }
}

// ---------------------------------------------------------------------------
// LayerNorm over last dim (256). One 256-thread block per row.
// ---------------------------------------------------------------------------
__device__ __forceinline__ void ln_row(const float* __restrict__ in,
                                       const float* __restrict__ g,
                                       const float* __restrict__ b,
                                       float* __restrict__ out)
{
    const int row = blockIdx.x;
    const int t   = threadIdx.x;
    float v = in[(size_t)row * DDIM + t];

    float s = v;
#pragma unroll
    for (int o = 16; o > 0; o >>= 1) s += __shfl_xor_sync(0xffffffffu, s, o);
    __shared__ float r1[8], r2[8];
    if ((t & 31) == 0) r1[t >> 5] = s;
    __syncthreads();
    float tot = 0.0f;
#pragma unroll
    for (int i = 0; i < 8; i++) tot += r1[i];
    const float mu = tot * (1.0f / 256.0f);

    const float d = v - mu;
    float s2 = d * d;
#pragma unroll
    for (int o = 16; o > 0; o >>= 1) s2 += __shfl_xor_sync(0xffffffffu, s2, o);
    if ((t & 31) == 0) r2[t >> 5] = s2;
    __syncthreads();
    float tv = 0.0f;
#pragma unroll
    for (int i = 0; i < 8; i++) tv += r2[i];
    const float var = tv * (1.0f / 256.0f);

    out[(size_t)row * DDIM + t] = d * rsqrtf(var + 1e-5f) * g[t] + b[t];
}

__global__ void ln1_kernel(const float* __restrict__ g, const float* __restrict__ b)
{
    ln_row(g_U, g, b, g_Hh);
}

__global__ void ln2_kernel(const float* __restrict__ g, const float* __restrict__ b,
                           float* __restrict__ out)
{
    ln_row(g_V, g, b, out);
}

// ---------------------------------------------------------------------------
extern "C" void kernel_launch(void* const* d_in, const int* in_sizes, int n_in,
                              void* d_out, int out_size)
{
    const float* x     = (const float*)d_in[0];
    const float* w_mix = (const float*)d_in[1];
    const float* b_mix = (const float*)d_in[2];
    const float* g1    = (const float*)d_in[3];
    const float* b1    = (const float*)d_in[4];
    const float* w_ff1 = (const float*)d_in[5];
    const float* b_ff1 = (const float*)d_in[6];
    const float* w_ff2 = (const float*)d_in[7];
    const float* b_ff2 = (const float*)d_in[8];
    const float* g2    = (const float*)d_in[9];
    const float* b2    = (const float*)d_in[10];
    float* out = (float*)d_out;

    dim3 block(256);

    mix_gemm_tc<<<dim3(MROWS / BM, DDIM / BN), block>>>(x, w_mix, b_mix);
    ln1_kernel<<<MROWS, 256>>>(g1, b1);
    ffn1_tc<<<dim3(MROWS / BM, HDIM / BN), block>>>(w_ff1, b_ff1);
    ffn2_tc<<<dim3(MROWS / BM, DDIM / BN), block>>>(w_ff2, b_ff2);
    ln2_kernel<<<MROWS, 256>>>(g2, b2, out);
}

// round 16
// speedup vs baseline: 3.2209x; 1.0197x over previous
#include <cuda_runtime.h>
#include <math.h>

// Problem constants
#define BATCH 4
#define SEQ   4096
#define DDIM  256
#define HDIM  1024
#define TAPS  15
#define MROWS (BATCH*SEQ)   // 16384

// Tile config
#define BM 128
#define BN 128
#define BK 16
#define STAGES 4
#define AWORDS (BM*BK)      // 2048 words / stage (8KB)
#define BWORDS (BK*BN)      // 2048 words / stage (8KB)

// Scratch (device globals; referenced ONLY from device code — host-passing
// them gives the host shadow address on GB300/ATS).
__device__ float g_U  [MROWS * DDIM];
__device__ float g_Hh [MROWS * DDIM];
__device__ float g_Act[MROWS * HDIM];
__device__ float g_V  [MROWS * DDIM];

// ---------------------------------------------------------------------------
// cp.async helpers
// ---------------------------------------------------------------------------
__device__ __forceinline__ unsigned smem_u32p(const void* p) {
    return (unsigned)__cvta_generic_to_shared(p);
}
__device__ __forceinline__ void cp16(unsigned dst, const float* src) {
    asm volatile("cp.async.cg.shared.global [%0], [%1], 16;" :: "r"(dst), "l"(src));
}
__device__ __forceinline__ void cp16z(unsigned dst, const float* src, int sb) {
    asm volatile("cp.async.cg.shared.global [%0], [%1], 16, %2;" :: "r"(dst), "l"(src), "r"(sb));
}
#define CP_COMMIT() asm volatile("cp.async.commit_group;")
// STAGES=4: at iteration it, groups for slices it..it+2 are outstanding;
// allow <=2 pending so slice it is complete.
#define CP_WAITN()  asm volatile("cp.async.wait_group 2;")

__device__ __forceinline__ void mma8(float c[4], const unsigned a[4], const unsigned b[2]) {
    asm volatile(
        "mma.sync.aligned.m16n8k8.row.col.f32.tf32.tf32.f32 "
        "{%0,%1,%2,%3}, {%4,%5,%6,%7}, {%8,%9}, {%0,%1,%2,%3};\n"
        : "+f"(c[0]), "+f"(c[1]), "+f"(c[2]), "+f"(c[3])
        : "r"(a[0]), "r"(a[1]), "r"(a[2]), "r"(a[3]), "r"(b[0]), "r"(b[1]));
}

// ---------------------------------------------------------------------------
// Swizzled-layout compute of one BK=16 slice.
// A layout: word = row*16 + (((k>>2) ^ ((row>>1)&3))<<2) + (k&3).
// B layout: word = k*128 + (n ^ (8*(k&3))).
// Both conflict-free for the m16n8k8 fragment pattern (bank math verified).
// Warp layout: 8 warps = 2(m) x 4(n); warp tile 64x32 = 4x4 m16n8k8 frags.
// ---------------------------------------------------------------------------
__device__ __forceinline__ void compute_slice(const float* __restrict__ Asb,
                                              const float* __restrict__ Bsb,
                                              int m_w, int n_w, int lane,
                                              float acc[4][4][4])
{
    const int r  = lane >> 2;
    const int kq = lane & 3;
    const int cx = (r >> 1) & 3;               // A chunk xor (row-derived, invariant)
    const unsigned* A = (const unsigned*)Asb;
    const unsigned* B = (const unsigned*)Bsb;

#pragma unroll
    for (int ks = 0; ks < 2; ks++) {
        const int k0 = (((2 * ks + 0) ^ cx) << 2) + kq;   // j=0 word offset in row
        const int k1 = (((2 * ks + 1) ^ cx) << 2) + kq;   // j=1
        unsigned af[4][4], bf[4][2];
#pragma unroll
        for (int mi = 0; mi < 4; mi++) {
            const int row = m_w + mi * 16 + r;
            af[mi][0] = A[row * 16 + k0];
            af[mi][1] = A[(row + 8) * 16 + k0];
            af[mi][2] = A[row * 16 + k1];
            af[mi][3] = A[(row + 8) * 16 + k1];
        }
        const int kb0 = (8 * ks + kq) * 128;
        const int kb1 = (8 * ks + kq + 4) * 128;
#pragma unroll
        for (int ni = 0; ni < 4; ni++) {
            const int n = (n_w + ni * 8 + r) ^ (8 * kq);
            bf[ni][0] = B[kb0 + n];
            bf[ni][1] = B[kb1 + n];
        }
#pragma unroll
        for (int mi = 0; mi < 4; mi++)
#pragma unroll
            for (int ni = 0; ni < 4; ni++)
                mma8(acc[mi][ni], af[mi], bf[ni]);
    }
}

// Per-thread swizzled STS destinations. Each thread owns two ADJACENT logical
// 16B chunks (cn0, cn0+1). Swizzled slots are (cn0^X) and (cn0^X)^1 — the
// second chunk address is first ^ 16 BYTES (bit-4 flip), NOT first + 16.
__device__ __forceinline__ unsigned a_sts_base(const float* As0, int am, int ak0) {
    const int c0 = (ak0 >> 2) ^ ((am >> 1) & 3);
    return smem_u32p(As0 + am * 16 + (c0 << 2));
}
__device__ __forceinline__ unsigned b_sts_base(const float* Bs0, int bk, int bn0) {
    const int c0 = (bn0 >> 2) ^ (2 * (bk & 3));
    return smem_u32p(Bs0 + bk * 128 + (c0 << 2));
}

// ---------------------------------------------------------------------------
// Kernel 1: mix GEMM (causal local conv, im2col) + bias + residual -> g_U
// M=16384, K=15*256, N=256. Grid (128, 2), 256 threads.
// ---------------------------------------------------------------------------
__global__ void __launch_bounds__(256, 2) mix_gemm_tc(const float* __restrict__ x,
                                                      const float* __restrict__ w_mix,
                                                      const float* __restrict__ b_mix)
{
    __shared__ __align__(128) float As[STAGES][AWORDS];
    __shared__ __align__(128) float Bs[STAGES][BWORDS];

    const int tid  = threadIdx.x;
    const int lane = tid & 31, wid = tid >> 5;
    const int bm = blockIdx.x * BM, bn = blockIdx.y * BN;
    const int m_w = (wid >> 2) * 64, n_w = (wid & 3) * 32;

    const int bidx = bm / SEQ, n_base = bm % SEQ;
    const float* xb = x + (size_t)bidx * SEQ * DDIM;

    const int am = tid >> 1, ak0 = (tid & 1) * 8;
    const int bk = tid >> 4, bn0 = (tid & 15) * 8;
    const unsigned aDst = a_sts_base(As[0], am, ak0);
    const unsigned bDst = b_sts_base(Bs[0], bk, bn0);

    float acc[4][4][4];
#pragma unroll
    for (int i = 0; i < 4; i++)
#pragma unroll
        for (int j = 0; j < 4; j++)
#pragma unroll
            for (int q = 0; q < 4; q++) acc[i][j][q] = 0.0f;

    const int NIT = TAPS * (DDIM / BK);  // 240

    auto issue_load = [&](int it, int s) {
        const int tap = it >> 4;
        const int d0  = (it & 15) << 4;
        const int src = n_base + am + tap - 14;
        const int sb  = (src >= 0) ? 16 : 0;
        const float* gA = &xb[(size_t)(src >= 0 ? src : 0) * DDIM + d0 + ak0];
        const unsigned a = aDst + (unsigned)s * (AWORDS * 4);
        cp16z(a,       gA,     sb);
        cp16z(a ^ 16u, gA + 4, sb);
        const float* gB = w_mix + ((size_t)tap * DDIM + (d0 + bk)) * DDIM + bn + bn0;
        const unsigned b = bDst + (unsigned)s * (BWORDS * 4);
        cp16(b,       gB);
        cp16(b ^ 16u, gB + 4);
        CP_COMMIT();
    };

    for (int s = 0; s < STAGES - 1; s++) issue_load(s, s);
    for (int it = 0; it < NIT; ++it) {
        CP_WAITN();
        __syncthreads();
        const int nxt = it + STAGES - 1;
        if (nxt < NIT) issue_load(nxt, nxt % STAGES);
        else CP_COMMIT();
        compute_slice(As[it % STAGES], Bs[it % STAGES], m_w, n_w, lane, acc);
    }

    // epilogue: + b_mix + x residual -> g_U
#pragma unroll
    for (int mi = 0; mi < 4; mi++) {
        const int r0 = bm + m_w + mi * 16 + (lane >> 2);
#pragma unroll
        for (int ni = 0; ni < 4; ni++) {
            const int c = bn + n_w + ni * 8 + 2 * (lane & 3);
            float2 bb = *(const float2*)&b_mix[c];
            float2 x0 = *(const float2*)&x[(size_t)r0 * DDIM + c];
            float2 x1 = *(const float2*)&x[(size_t)(r0 + 8) * DDIM + c];
            float2 o0 = { acc[mi][ni][0] + bb.x + x0.x, acc[mi][ni][1] + bb.y + x0.y };
            float2 o1 = { acc[mi][ni][2] + bb.x + x1.x, acc[mi][ni][3] + bb.y + x1.y };
            *(float2*)&g_U[(size_t)r0 * DDIM + c] = o0;
            *(float2*)&g_U[(size_t)(r0 + 8) * DDIM + c] = o1;
        }
    }
}

// ---------------------------------------------------------------------------
// Kernel 3: FFN1 = gelu(h @ W1 + b_ff1). M=16384, K=256, N=1024. Grid (128, 8).
// ---------------------------------------------------------------------------
__global__ void __launch_bounds__(256, 2) ffn1_tc(const float* __restrict__ W1,
                                                  const float* __restrict__ bff1)
{
    __shared__ __align__(128) float As[STAGES][AWORDS];
    __shared__ __align__(128) float Bs[STAGES][BWORDS];

    const int tid  = threadIdx.x;
    const int lane = tid & 31, wid = tid >> 5;
    const int bm = blockIdx.x * BM, bn = blockIdx.y * BN;
    const int m_w = (wid >> 2) * 64, n_w = (wid & 3) * 32;

    const int am = tid >> 1, ak0 = (tid & 1) * 8;
    const int bk = tid >> 4, bn0 = (tid & 15) * 8;
    const unsigned aDst = a_sts_base(As[0], am, ak0);
    const unsigned bDst = b_sts_base(Bs[0], bk, bn0);

    float acc[4][4][4];
#pragma unroll
    for (int i = 0; i < 4; i++)
#pragma unroll
        for (int j = 0; j < 4; j++)
#pragma unroll
            for (int q = 0; q < 4; q++) acc[i][j][q] = 0.0f;

    const int NIT = DDIM / BK;  // 16

    auto issue_load = [&](int it, int s) {
        const int k0 = it << 4;
        const float* gA = &g_Hh[(size_t)(bm + am) * DDIM + k0 + ak0];
        const unsigned a = aDst + (unsigned)s * (AWORDS * 4);
        cp16(a,       gA);
        cp16(a ^ 16u, gA + 4);
        const float* gB = &W1[(size_t)(k0 + bk) * HDIM + bn + bn0];
        const unsigned b = bDst + (unsigned)s * (BWORDS * 4);
        cp16(b,       gB);
        cp16(b ^ 16u, gB + 4);
        CP_COMMIT();
    };

    for (int s = 0; s < STAGES - 1; s++) issue_load(s, s);
    for (int it = 0; it < NIT; ++it) {
        CP_WAITN();
        __syncthreads();
        const int nxt = it + STAGES - 1;
        if (nxt < NIT) issue_load(nxt, nxt % STAGES);
        else CP_COMMIT();
        compute_slice(As[it % STAGES], Bs[it % STAGES], m_w, n_w, lane, acc);
    }

    const float kInvSqrt2 = 0.70710678118654752f;
#pragma unroll
    for (int mi = 0; mi < 4; mi++) {
        const int r0 = bm + m_w + mi * 16 + (lane >> 2);
#pragma unroll
        for (int ni = 0; ni < 4; ni++) {
            const int c = bn + n_w + ni * 8 + 2 * (lane & 3);
            float2 bb = *(const float2*)&bff1[c];
            float v00 = acc[mi][ni][0] + bb.x;
            float v01 = acc[mi][ni][1] + bb.y;
            float v10 = acc[mi][ni][2] + bb.x;
            float v11 = acc[mi][ni][3] + bb.y;
            float2 o0 = { 0.5f * v00 * (1.0f + erff(v00 * kInvSqrt2)),
                          0.5f * v01 * (1.0f + erff(v01 * kInvSqrt2)) };
            float2 o1 = { 0.5f * v10 * (1.0f + erff(v10 * kInvSqrt2)),
                          0.5f * v11 * (1.0f + erff(v11 * kInvSqrt2)) };
            *(float2*)&g_Act[(size_t)r0 * HDIM + c] = o0;
            *(float2*)&g_Act[(size_t)(r0 + 8) * HDIM + c] = o1;
        }
    }
}

// ---------------------------------------------------------------------------
// Kernel 4: FFN2 = Act @ W2 + b_ff2 + h. M=16384, K=1024, N=256. Grid (128, 2).
// ---------------------------------------------------------------------------
__global__ void __launch_bounds__(256, 2) ffn2_tc(const float* __restrict__ W2,
                                                  const float* __restrict__ bff2)
{
    __shared__ __align__(128) float As[STAGES][AWORDS];
    __shared__ __align__(128) float Bs[STAGES][BWORDS];

    const int tid  = threadIdx.x;
    const int lane = tid & 31, wid = tid >> 5;
    const int bm = blockIdx.x * BM, bn = blockIdx.y * BN;
    const int m_w = (wid >> 2) * 64, n_w = (wid & 3) * 32;

    const int am = tid >> 1, ak0 = (tid & 1) * 8;
    const int bk = tid >> 4, bn0 = (tid & 15) * 8;
    const unsigned aDst = a_sts_base(As[0], am, ak0);
    const unsigned bDst = b_sts_base(Bs[0], bk, bn0);

    float acc[4][4][4];
#pragma unroll
    for (int i = 0; i < 4; i++)
#pragma unroll
        for (int j = 0; j < 4; j++)
#pragma unroll
            for (int q = 0; q < 4; q++) acc[i][j][q] = 0.0f;

    const int NIT = HDIM / BK;  // 64

    auto issue_load = [&](int it, int s) {
        const int k0 = it << 4;
        const float* gA = &g_Act[(size_t)(bm + am) * HDIM + k0 + ak0];
        const unsigned a = aDst + (unsigned)s * (AWORDS * 4);
        cp16(a,       gA);
        cp16(a ^ 16u, gA + 4);
        const float* gB = &W2[(size_t)(k0 + bk) * DDIM + bn + bn0];
        const unsigned b = bDst + (unsigned)s * (BWORDS * 4);
        cp16(b,       gB);
        cp16(b ^ 16u, gB + 4);
        CP_COMMIT();
    };

    for (int s = 0; s < STAGES - 1; s++) issue_load(s, s);
    for (int it = 0; it < NIT; ++it) {
        CP_WAITN();
        __syncthreads();
        const int nxt = it + STAGES - 1;
        if (nxt < NIT) issue_load(nxt, nxt % STAGES);
        else CP_COMMIT();
        compute_slice(As[it % STAGES], Bs[it % STAGES], m_w, n_w, lane, acc);
    }

    // epilogue: + b_ff2 + h residual -> g_V
#pragma unroll
    for (int mi = 0; mi < 4; mi++) {
        const int r0 = bm + m_w + mi * 16 + (lane >> 2);
#pragma unroll
        for (int ni = 0; ni < 4; ni++) {
            const int c = bn + n_w + ni * 8 + 2 * (lane & 3);
            float2 bb = *(const float2*)&bff2[c];
            float2 h0 = *(const float2*)&g_Hh[(size_t)r0 * DDIM + c];
            float2 h1 = *(const float2*)&g_Hh[(size_t)(r0 + 8) * DDIM + c];
            float2 o0 = { acc[mi][ni][0] + bb.x + h0.x, acc[mi][ni][1] + bb.y + h0.y };
            float2 o1 = { acc[mi][ni][2] + bb.x + h1.x, acc[mi][ni][3] + bb.y + h1.y };
            *(float2*)&g_V[(size_t)r0 * DDIM + c] = o0;
            *(float2*)&g_V[(size_t)(r0 + 8) * DDIM + c] = o1;
        }
    }
}

// ---------------------------------------------------------------------------
// LayerNorm over last dim (256). One 256-thread block per row.
// ---------------------------------------------------------------------------
__device__ __forceinline__ void ln_row(const float* __restrict__ in,
                                       const float* __restrict__ g,
                                       const float* __restrict__ b,
                                       float* __restrict__ out)
{
    const int row = blockIdx.x;
    const int t   = threadIdx.x;
    float v = in[(size_t)row * DDIM + t];

    float s = v;
#pragma unroll
    for (int o = 16; o > 0; o >>= 1) s += __shfl_xor_sync(0xffffffffu, s, o);
    __shared__ float r1[8], r2[8];
    if ((t & 31) == 0) r1[t >> 5] = s;
    __syncthreads();
    float tot = 0.0f;
#pragma unroll
    for (int i = 0; i < 8; i++) tot += r1[i];
    const float mu = tot * (1.0f / 256.0f);

    const float d = v - mu;
    float s2 = d * d;
#pragma unroll
    for (int o = 16; o > 0; o >>= 1) s2 += __shfl_xor_sync(0xffffffffu, s2, o);
    if ((t & 31) == 0) r2[t >> 5] = s2;
    __syncthreads();
    float tv = 0.0f;
#pragma unroll
    for (int i = 0; i < 8; i++) tv += r2[i];
    const float var = tv * (1.0f / 256.0f);

    out[(size_t)row * DDIM + t] = d * rsqrtf(var + 1e-5f) * g[t] + b[t];
}

__global__ void ln1_kernel(const float* __restrict__ g, const float* __restrict__ b)
{
    ln_row(g_U, g, b, g_Hh);
}

__global__ void ln2_kernel(const float* __restrict__ g, const float* __restrict__ b,
                           float* __restrict__ out)
{
    ln_row(g_V, g, b, out);
}

// ---------------------------------------------------------------------------
extern "C" void kernel_launch(void* const* d_in, const int* in_sizes, int n_in,
                              void* d_out, int out_size)
{
    const float* x     = (const float*)d_in[0];
    const float* w_mix = (const float*)d_in[1];
    const float* b_mix = (const float*)d_in[2];
    const float* g1    = (const float*)d_in[3];
    const float* b1    = (const float*)d_in[4];
    const float* w_ff1 = (const float*)d_in[5];
    const float* b_ff1 = (const float*)d_in[6];
    const float* w_ff2 = (const float*)d_in[7];
    const float* b_ff2 = (const float*)d_in[8];
    const float* g2    = (const float*)d_in[9];
    const float* b2    = (const float*)d_in[10];
    float* out = (float*)d_out;

    dim3 block(256);

    mix_gemm_tc<<<dim3(MROWS / BM, DDIM / BN), block>>>(x, w_mix, b_mix);
    ln1_kernel<<<MROWS, 256>>>(g1, b1);
    ffn1_tc<<<dim3(MROWS / BM, HDIM / BN), block>>>(w_ff1, b_ff1);
    ffn2_tc<<<dim3(MROWS / BM, DDIM / BN), block>>>(w_ff2, b_ff2);
    ln2_kernel<<<MROWS, 256>>>(g2, b2, out);
}